// round 1
// baseline (speedup 1.0000x reference)
#include <cuda_runtime.h>

#define NN 2048
#define EE 65536
#define WORDS 64            // 2048 bits / 32
#define C_IN 128
#define H1D 3200
#define H2D 1600
#define ODIM 32

// ---------------- scratch (device globals: allocation-free) ----------------
__device__ unsigned g_adj[NN * WORDS];   // adjacency bitmap, row = dst, col = src
__device__ unsigned g_rA [NN * WORDS];   // reach bitsets (ping)
__device__ unsigned g_rB [NN * WORDS];   // reach bitsets (pong)
__device__ float    g_dvec[NN];          // deg^-1/2
__device__ float    g_u  [NN * H2D];     // u = d .* feat
__device__ float    g_va [NN * H2D];     // Horner ping
__device__ float    g_vb [NN * H2D];     // Horner pong
__device__ float    g_z  [NN * C_IN];    // layer-1 propagated features
__device__ float    g_h1 [NN * H1D];
__device__ float    g_gg [NN * H2D];     // h1 @ W2
__device__ float    g_h2 [NN * H2D];
__device__ float    g_g3 [NN * ODIM];    // h2 @ W3

// ---------------- small utility kernels ----------------
__global__ void k_zero_u32(unsigned* p, int n) {
    int i = blockIdx.x * blockDim.x + threadIdx.x;
    if (i < n) p[i] = 0u;
}

__global__ void k_build_adj(const int* __restrict__ ei, unsigned* __restrict__ adj) {
    int e = blockIdx.x * blockDim.x + threadIdx.x;
    if (e < EE) {
        int src = ei[e];        // edge_index[0] = col (src)
        int dst = ei[EE + e];   // edge_index[1] = row (dst)
        atomicOr(&adj[dst * WORDS + (src >> 5)], 1u << (src & 31));
    }
}

// reach init: R = supp(I + A)
__global__ void k_reach_init(const unsigned* __restrict__ adj, unsigned* __restrict__ R) {
    int i = blockIdx.x * blockDim.x + threadIdx.x;
    if (i < NN * WORDS) {
        int u = i >> 6, w = i & 63;
        unsigned v = adj[i];
        if ((u >> 5) == w) v |= 1u << (u & 31);
        R[i] = v;
    }
}

// Horner boolean step: Rnew[u] = I_u | OR_{v in adjrow(u)} Rold[v]
__global__ void k_reach_iter(const unsigned* __restrict__ adj,
                             const unsigned* __restrict__ Rold,
                             unsigned* __restrict__ Rnew) {
    __shared__ unsigned arow[WORDS];
    int u = blockIdx.x;
    int w = threadIdx.x;          // 64 threads, one output word each
    arow[w] = adj[u * WORDS + w];
    __syncthreads();
    unsigned acc = ((u >> 5) == w) ? (1u << (u & 31)) : 0u;
    for (int ww = 0; ww < WORDS; ++ww) {
        unsigned bits = arow[ww];
        while (bits) {
            int b = __ffs(bits) - 1;
            bits &= bits - 1;
            int v = ww * 32 + b;
            acc |= Rold[v * WORDS + w];   // coalesced across 64 threads
        }
    }
    Rnew[u * WORDS + w] = acc;
}

__global__ void k_deg(const unsigned* __restrict__ R, float* __restrict__ d) {
    int u = blockIdx.x * blockDim.x + threadIdx.x;
    if (u < NN) {
        int c = 0;
        #pragma unroll 8
        for (int w = 0; w < WORDS; ++w) c += __popc(R[u * WORDS + w]);
        d[u] = (c > 0) ? rsqrtf((float)c) : 0.0f;
    }
}

// u = d .* feat ; v = u  (Horner seed)
__global__ void k_scale_u(const float* __restrict__ feat, const float* __restrict__ d,
                          float* __restrict__ u, float* __restrict__ v, int C) {
    int i = blockIdx.x * blockDim.x + threadIdx.x;
    if (i < NN * C) {
        float val = d[i / C] * feat[i];
        u[i] = val;
        v[i] = val;
    }
}

// Horner SpMM step: vout[r] = u[r] + wk * sum_{nb in adjrow(r)} vin[nb]
// Vectorized float4 over channels. NV = ceil(C/4/256).
template <int NV>
__global__ __launch_bounds__(256)
void k_spmm(const unsigned* __restrict__ adj,
            const float* __restrict__ vin,
            const float* __restrict__ uvec,
            float* __restrict__ vout,
            const float* __restrict__ wvec, int widx, int C) {
    __shared__ unsigned arow[WORDS];
    int u = blockIdx.x;
    int t = threadIdx.x;
    if (t < WORDS) arow[t] = adj[u * WORDS + t];
    __syncthreads();
    const int C4 = C >> 2;
    float wk = __ldg(&wvec[widx]);

    float4 acc[NV];
    #pragma unroll
    for (int j = 0; j < NV; ++j) acc[j] = make_float4(0.f, 0.f, 0.f, 0.f);

    for (int ww = 0; ww < WORDS; ++ww) {
        unsigned bits = arow[ww];
        while (bits) {
            int b = __ffs(bits) - 1;
            bits &= bits - 1;
            const float4* row = reinterpret_cast<const float4*>(vin + (size_t)(ww * 32 + b) * C);
            #pragma unroll
            for (int j = 0; j < NV; ++j) {
                int idx = t + j * 256;
                if (idx < C4) {
                    float4 r = __ldg(&row[idx]);
                    acc[j].x += r.x; acc[j].y += r.y; acc[j].z += r.z; acc[j].w += r.w;
                }
            }
        }
    }
    const float4* urow = reinterpret_cast<const float4*>(uvec + (size_t)u * C);
    float4* orow = reinterpret_cast<float4*>(vout + (size_t)u * C);
    #pragma unroll
    for (int j = 0; j < NV; ++j) {
        int idx = t + j * 256;
        if (idx < C4) {
            float4 uu = urow[idx];
            float4 o;
            o.x = uu.x + wk * acc[j].x;
            o.y = uu.y + wk * acc[j].y;
            o.z = uu.z + wk * acc[j].z;
            o.w = uu.w + wk * acc[j].w;
            orow[idx] = o;
        }
    }
}

// z = w0 * d .* v   (pre-GEMM scale, layer 1)
__global__ void k_scale_z(const float* __restrict__ v, const float* __restrict__ d,
                          const float* __restrict__ wvec, float* __restrict__ z, int C) {
    int i = blockIdx.x * blockDim.x + threadIdx.x;
    if (i < NN * C) z[i] = wvec[0] * d[i / C] * v[i];
}

// out = relu(w0 * d .* v + bias)   (post-propagation epilogue, layers 2/3)
__global__ void k_final(const float* __restrict__ v, const float* __restrict__ d,
                        const float* __restrict__ wvec, const float* __restrict__ bias,
                        float* __restrict__ out, int C) {
    int i = blockIdx.x * blockDim.x + threadIdx.x;
    if (i < NN * C) {
        float val = wvec[0] * d[i / C] * v[i] + bias[i % C];
        out[i] = fmaxf(val, 0.0f);
    }
}

// ---------------- fp32 tiled GEMM: C = A[M,K] @ B[K,N] (+bias, relu) ----------------
#define BM 128
#define BN 128
#define BK 16
#define TM 8
#define TN 8

__global__ __launch_bounds__(256)
void k_gemm(const float* __restrict__ A, const float* __restrict__ B,
            const float* __restrict__ bias, float* __restrict__ Cout,
            int M, int Nd, int K, int do_bias_relu) {
    __shared__ float As[BK][BM + 4];
    __shared__ float Bs[BK][BN];

    int tid = threadIdx.x;
    int tx = tid & 15;      // n group
    int ty = tid >> 4;      // m group
    int m0 = blockIdx.y * BM;
    int n0 = blockIdx.x * BN;

    float acc[TM][TN];
    #pragma unroll
    for (int i = 0; i < TM; ++i)
        #pragma unroll
        for (int j = 0; j < TN; ++j) acc[i][j] = 0.f;

    for (int k0 = 0; k0 < K; k0 += BK) {
        // A tile: 128 rows x 16 k  (512 float4 total, 2 per thread), stored transposed
        #pragma unroll
        for (int it = 0; it < 2; ++it) {
            int idx = tid + it * 256;
            int row = idx >> 2;
            int c4  = idx & 3;
            float4 va = *reinterpret_cast<const float4*>(A + (size_t)(m0 + row) * K + k0 + c4 * 4);
            As[c4 * 4 + 0][row] = va.x;
            As[c4 * 4 + 1][row] = va.y;
            As[c4 * 4 + 2][row] = va.z;
            As[c4 * 4 + 3][row] = va.w;
        }
        // B tile: 16 k x 128 n  (512 float4, 2 per thread), N-guarded
        #pragma unroll
        for (int it = 0; it < 2; ++it) {
            int idx = tid + it * 256;
            int kr = idx >> 5;
            int c4 = idx & 31;
            int n  = n0 + c4 * 4;
            float4 vb = make_float4(0.f, 0.f, 0.f, 0.f);
            if (n < Nd) vb = *reinterpret_cast<const float4*>(B + (size_t)(k0 + kr) * Nd + n);
            *reinterpret_cast<float4*>(&Bs[kr][c4 * 4]) = vb;
        }
        __syncthreads();

        #pragma unroll
        for (int k = 0; k < BK; ++k) {
            float a[TM], b[TN];
            float4 a0 = *reinterpret_cast<const float4*>(&As[k][ty * TM]);
            float4 a1 = *reinterpret_cast<const float4*>(&As[k][ty * TM + 4]);
            a[0]=a0.x; a[1]=a0.y; a[2]=a0.z; a[3]=a0.w;
            a[4]=a1.x; a[5]=a1.y; a[6]=a1.z; a[7]=a1.w;
            float4 b0 = *reinterpret_cast<const float4*>(&Bs[k][tx * TN]);
            float4 b1 = *reinterpret_cast<const float4*>(&Bs[k][tx * TN + 4]);
            b[0]=b0.x; b[1]=b0.y; b[2]=b0.z; b[3]=b0.w;
            b[4]=b1.x; b[5]=b1.y; b[6]=b1.z; b[7]=b1.w;
            #pragma unroll
            for (int i = 0; i < TM; ++i)
                #pragma unroll
                for (int j = 0; j < TN; ++j)
                    acc[i][j] += a[i] * b[j];
        }
        __syncthreads();
    }

    #pragma unroll
    for (int i = 0; i < TM; ++i) {
        int m = m0 + ty * TM + i;
        #pragma unroll
        for (int j = 0; j < TN; ++j) {
            int n = n0 + tx * TN + j;
            if (n < Nd) {
                float v = acc[i][j];
                if (do_bias_relu) {
                    v += bias[n];
                    v = fmaxf(v, 0.f);
                }
                Cout[(size_t)m * Nd + n] = v;
            }
        }
    }
}

// ---------------- host-side orchestration ----------------
static float* run_prop(const unsigned* adj, const float* dvec,
                       const float* feat, const float* w, int C,
                       float* u, float* va, float* vb) {
    int total = NN * C;
    k_scale_u<<<(total + 255) / 256, 256>>>(feat, dvec, u, va, C);
    float* vin = va;
    float* vout = vb;
    for (int k = 5; k >= 1; --k) {
        if (C == H2D) k_spmm<2><<<NN, 256>>>(adj, vin, u, vout, w, k, C);
        else          k_spmm<1><<<NN, 256>>>(adj, vin, u, vout, w, k, C);
        float* t = vin; vin = vout; vout = t;
    }
    return vin;   // holds Horner result v;  propagated = w[0] * d .* v
}

extern "C" void kernel_launch(void* const* d_in, const int* in_sizes, int n_in,
                              void* d_out, int out_size) {
    const float* x  = (const float*)d_in[0];
    const int*   ei = (const int*)  d_in[1];
    const float* w1 = (const float*)d_in[2];
    const float* w2 = (const float*)d_in[3];
    const float* w3 = (const float*)d_in[4];
    const float* W1 = (const float*)d_in[5];
    const float* b1 = (const float*)d_in[6];
    const float* W2 = (const float*)d_in[7];
    const float* b2 = (const float*)d_in[8];
    const float* W3 = (const float*)d_in[9];
    const float* b3 = (const float*)d_in[10];
    float* out = (float*)d_out;

    unsigned *adj, *rA, *rB;
    float *dvec, *u, *va, *vb, *z, *h1, *gg, *h2, *g3;
    cudaGetSymbolAddress((void**)&adj,  g_adj);
    cudaGetSymbolAddress((void**)&rA,   g_rA);
    cudaGetSymbolAddress((void**)&rB,   g_rB);
    cudaGetSymbolAddress((void**)&dvec, g_dvec);
    cudaGetSymbolAddress((void**)&u,    g_u);
    cudaGetSymbolAddress((void**)&va,   g_va);
    cudaGetSymbolAddress((void**)&vb,   g_vb);
    cudaGetSymbolAddress((void**)&z,    g_z);
    cudaGetSymbolAddress((void**)&h1,   g_h1);
    cudaGetSymbolAddress((void**)&gg,   g_gg);
    cudaGetSymbolAddress((void**)&h2,   g_h2);
    cudaGetSymbolAddress((void**)&g3,   g_g3);

    // ---- adjacency bitmap (dedup) + boolean reach + deg^-1/2 ----
    k_zero_u32<<<(NN * WORDS + 255) / 256, 256>>>(adj, NN * WORDS);
    k_build_adj<<<EE / 256, 256>>>(ei, adj);
    k_reach_init<<<(NN * WORDS + 255) / 256, 256>>>(adj, rA);   // I + A
    k_reach_iter<<<NN, 64>>>(adj, rA, rB);                      // .. + A^2
    k_reach_iter<<<NN, 64>>>(adj, rB, rA);                      // .. + A^3
    k_reach_iter<<<NN, 64>>>(adj, rA, rB);                      // .. + A^4
    k_reach_iter<<<NN, 64>>>(adj, rB, rA);                      // .. + A^5
    k_deg<<<(NN + 255) / 256, 256>>>(rA, dvec);

    // ---- layer 1: h1 = relu((M1_hat x) W1 + b1) ----
    {
        float* v = run_prop(adj, dvec, x, w1, C_IN, u, va, vb);
        k_scale_z<<<(NN * C_IN + 255) / 256, 256>>>(v, dvec, w1, z, C_IN);
        dim3 grid((H1D + BN - 1) / BN, NN / BM);
        k_gemm<<<grid, 256>>>(z, W1, b1, h1, NN, H1D, C_IN, 1);
    }

    // ---- layer 2: h2 = relu(M2_hat (h1 W2) + b2) ----
    {
        dim3 grid((H2D + BN - 1) / BN, NN / BM);
        k_gemm<<<grid, 256>>>(h1, W2, (const float*)0, gg, NN, H2D, H1D, 0);
        float* v = run_prop(adj, dvec, gg, w2, H2D, u, va, vb);
        k_final<<<(NN * H2D + 255) / 256, 256>>>(v, dvec, w2, b2, h2, H2D);
    }

    // ---- layer 3: out = relu(M3_hat (h2 W3) + b3) ----
    {
        dim3 grid((ODIM + BN - 1) / BN, NN / BM);
        k_gemm<<<grid, 256>>>(h2, W3, (const float*)0, g3, NN, ODIM, H2D, 0);
        float* v = run_prop(adj, dvec, g3, w3, ODIM, u, va, vb);
        k_final<<<(NN * ODIM + 255) / 256, 256>>>(v, dvec, w3, b3, out, ODIM);
    }
}

// round 3
// speedup vs baseline: 1.6742x; 1.6742x over previous
#include <cuda_runtime.h>

#define NN 2048
#define EE 65536
#define WORDS 64            // 2048 bits / 32
#define NBMAX 2048          // worst-case neighbors per row (full safety)
#define C_IN 128
#define H1D 3200
#define H2D 1600
#define ODIM 32
#define SK3 4               // split-K factor for GEMM3

// ---------------- scratch (device globals: allocation-free) ----------------
__device__ unsigned g_adj[NN * WORDS];
__device__ unsigned g_rA [NN * WORDS];
__device__ unsigned g_rB [NN * WORDS];
__device__ int      g_nbr[(size_t)NN * NBMAX];
__device__ int      g_cnt[NN];
__device__ float    g_dvec[NN];
__device__ float    g_u  [NN * H2D];
__device__ float    g_va [NN * H2D];
__device__ float    g_vb [NN * H2D];
__device__ float    g_z  [NN * C_IN];
__device__ float    g_h1 [NN * H1D];
__device__ float    g_gg [NN * H2D];
__device__ float    g_h2 [NN * H2D];
__device__ float    g_g3 [NN * ODIM];
__device__ float    g_g3p[SK3 * NN * ODIM];

// ---------------- utility kernels ----------------
__global__ void k_zero_u32(unsigned* p, int n) {
    int i = blockIdx.x * blockDim.x + threadIdx.x;
    if (i < n) p[i] = 0u;
}

__global__ void k_build_adj(const int* __restrict__ ei, unsigned* __restrict__ adj) {
    int e = blockIdx.x * blockDim.x + threadIdx.x;
    if (e < EE) {
        int src = ei[e];
        int dst = ei[EE + e];
        atomicOr(&adj[dst * WORDS + (src >> 5)], 1u << (src & 31));
    }
}

// per-row sorted neighbor list from bitmap (deterministic)
__global__ void k_build_list(const unsigned* __restrict__ adj,
                             int* __restrict__ nbr, int* __restrict__ cnt) {
    int u = blockIdx.x * blockDim.x + threadIdx.x;
    if (u >= NN) return;
    int c = 0;
    int* out = nbr + (size_t)u * NBMAX;
    for (int w = 0; w < WORDS; ++w) {
        unsigned bits = adj[u * WORDS + w];
        while (bits) {
            int b = __ffs(bits) - 1;
            bits &= bits - 1;
            if (c < NBMAX) out[c] = w * 32 + b;
            ++c;
        }
    }
    cnt[u] = (c < NBMAX) ? c : NBMAX;
}

__global__ void k_reach_init(const unsigned* __restrict__ adj, unsigned* __restrict__ R) {
    int i = blockIdx.x * blockDim.x + threadIdx.x;
    if (i < NN * WORDS) {
        int u = i >> 6, w = i & 63;
        unsigned v = adj[i];
        if ((u >> 5) == w) v |= 1u << (u & 31);
        R[i] = v;
    }
}

// Rnew[u] = I_u | OR_{v in nbr(u)} Rold[v]   — MLP via 4x unroll
__global__ void k_reach_iter(const int* __restrict__ nbr, const int* __restrict__ cnt,
                             const unsigned* __restrict__ Rold, unsigned* __restrict__ Rnew) {
    int u = blockIdx.x;
    int w = threadIdx.x;            // 64 threads
    int n = __ldg(&cnt[u]);
    const int* list = nbr + (size_t)u * NBMAX;
    unsigned acc = ((u >> 5) == w) ? (1u << (u & 31)) : 0u;
    int j = 0;
    for (; j + 4 <= n; j += 4) {
        int v0 = __ldg(list + j + 0), v1 = __ldg(list + j + 1);
        int v2 = __ldg(list + j + 2), v3 = __ldg(list + j + 3);
        unsigned r0 = Rold[v0 * WORDS + w];
        unsigned r1 = Rold[v1 * WORDS + w];
        unsigned r2 = Rold[v2 * WORDS + w];
        unsigned r3 = Rold[v3 * WORDS + w];
        acc |= (r0 | r1) | (r2 | r3);
    }
    for (; j < n; ++j) acc |= Rold[__ldg(list + j) * WORDS + w];
    Rnew[u * WORDS + w] = acc;
}

__global__ void k_deg(const unsigned* __restrict__ R, float* __restrict__ d) {
    int u = blockIdx.x * blockDim.x + threadIdx.x;
    if (u < NN) {
        int c = 0;
        #pragma unroll 8
        for (int w = 0; w < WORDS; ++w) c += __popc(R[u * WORDS + w]);
        d[u] = (c > 0) ? rsqrtf((float)c) : 0.0f;
    }
}

__global__ void k_scale_u(const float* __restrict__ feat, const float* __restrict__ d,
                          float* __restrict__ u, float* __restrict__ v, int C) {
    int i = blockIdx.x * blockDim.x + threadIdx.x;
    if (i < NN * C) {
        float val = d[i / C] * feat[i];
        u[i] = val;
        v[i] = val;
    }
}

// Horner SpMM: vout[r] = u[r] + wk * sum_{nb} vin[nb]  (neighbor-list, 4x unroll)
template <int NV>
__global__ __launch_bounds__(256)
void k_spmm(const int* __restrict__ nbr, const int* __restrict__ cnt,
            const float* __restrict__ vin, const float* __restrict__ uvec,
            float* __restrict__ vout,
            const float* __restrict__ wvec, int widx, int C) {
    int u = blockIdx.x;
    int t = threadIdx.x;
    int n = __ldg(&cnt[u]);
    const int* list = nbr + (size_t)u * NBMAX;
    const int C4 = C >> 2;
    float wk = __ldg(&wvec[widx]);

    float4 acc[NV];
    #pragma unroll
    for (int q = 0; q < NV; ++q) acc[q] = make_float4(0.f, 0.f, 0.f, 0.f);

    int j = 0;
    for (; j + 4 <= n; j += 4) {
        int v0 = __ldg(list + j + 0), v1 = __ldg(list + j + 1);
        int v2 = __ldg(list + j + 2), v3 = __ldg(list + j + 3);
        const float4* r0 = reinterpret_cast<const float4*>(vin + (size_t)v0 * C);
        const float4* r1 = reinterpret_cast<const float4*>(vin + (size_t)v1 * C);
        const float4* r2 = reinterpret_cast<const float4*>(vin + (size_t)v2 * C);
        const float4* r3 = reinterpret_cast<const float4*>(vin + (size_t)v3 * C);
        #pragma unroll
        for (int q = 0; q < NV; ++q) {
            int idx = t + q * 256;
            if (idx < C4) {
                float4 x0 = __ldg(r0 + idx);
                float4 x1 = __ldg(r1 + idx);
                float4 x2 = __ldg(r2 + idx);
                float4 x3 = __ldg(r3 + idx);
                acc[q].x += (x0.x + x1.x) + (x2.x + x3.x);
                acc[q].y += (x0.y + x1.y) + (x2.y + x3.y);
                acc[q].z += (x0.z + x1.z) + (x2.z + x3.z);
                acc[q].w += (x0.w + x1.w) + (x2.w + x3.w);
            }
        }
    }
    for (; j < n; ++j) {
        int v = __ldg(list + j);
        const float4* r = reinterpret_cast<const float4*>(vin + (size_t)v * C);
        #pragma unroll
        for (int q = 0; q < NV; ++q) {
            int idx = t + q * 256;
            if (idx < C4) {
                float4 x = __ldg(r + idx);
                acc[q].x += x.x; acc[q].y += x.y; acc[q].z += x.z; acc[q].w += x.w;
            }
        }
    }
    const float4* urow = reinterpret_cast<const float4*>(uvec + (size_t)u * C);
    float4* orow = reinterpret_cast<float4*>(vout + (size_t)u * C);
    #pragma unroll
    for (int q = 0; q < NV; ++q) {
        int idx = t + q * 256;
        if (idx < C4) {
            float4 uu = urow[idx];
            float4 o;
            o.x = uu.x + wk * acc[q].x;
            o.y = uu.y + wk * acc[q].y;
            o.z = uu.z + wk * acc[q].z;
            o.w = uu.w + wk * acc[q].w;
            orow[idx] = o;
        }
    }
}

__global__ void k_scale_z(const float* __restrict__ v, const float* __restrict__ d,
                          const float* __restrict__ wvec, float* __restrict__ z, int C) {
    int i = blockIdx.x * blockDim.x + threadIdx.x;
    if (i < NN * C) z[i] = wvec[0] * d[i / C] * v[i];
}

__global__ void k_final(const float* __restrict__ v, const float* __restrict__ d,
                        const float* __restrict__ wvec, const float* __restrict__ bias,
                        float* __restrict__ out, int C) {
    int i = blockIdx.x * blockDim.x + threadIdx.x;
    if (i < NN * C) {
        float val = wvec[0] * d[i / C] * v[i] + bias[i % C];
        out[i] = fmaxf(val, 0.0f);
    }
}

__global__ void k_reduce_sk(const float* __restrict__ p, float* __restrict__ out, int n) {
    int i = blockIdx.x * blockDim.x + threadIdx.x;
    if (i < n) {
        float s = 0.f;
        #pragma unroll
        for (int k = 0; k < SK3; ++k) s += p[(size_t)k * n + i];
        out[i] = s;
    }
}

// ---------------- fp32 GEMM, cp.async double-buffered ----------------
#define BM 128
#define BK 16

__device__ __forceinline__ void cpasync16(void* s, const void* g, bool p) {
    unsigned sa = (unsigned)__cvta_generic_to_shared(s);
    asm volatile("cp.async.cg.shared.global [%0], [%1], 16, %2;"
                 :: "r"(sa), "l"(g), "r"(p ? 16 : 0));
}
__device__ __forceinline__ void cp_commit() {
    asm volatile("cp.async.commit_group;" ::: "memory");
}
__device__ __forceinline__ void cp_wait0() {
    asm volatile("cp.async.wait_group 0;" ::: "memory");
}
__device__ __forceinline__ void cp_wait1() {
    asm volatile("cp.async.wait_group 1;" ::: "memory");
}

// C[BMxBN_] tile GEMM. grid: (x = N tiles, y = M tiles, z = K splits).
// A row stride lda, B row stride ldb, C row stride ldc. Kloop per z-split.
// partStride: output offset per z (0 when grid.z==1). EPI: +bias, relu.
template<int BN_, int TN_, int EPI>
__global__ __launch_bounds__(256)
void k_gemm(const float* __restrict__ A, int lda,
            const float* __restrict__ B, int ldb,
            const float* __restrict__ bias,
            float* __restrict__ Cout, int ldc,
            int Nd, int Kloop, int partStride) {
    __shared__ float As[2][BM][BK];
    __shared__ float Bs[2][BK][BN_];

    const int tid = threadIdx.x;
    const int tx = tid & 15;
    const int ty = tid >> 4;
    const int m0 = blockIdx.y * BM;
    const int n0 = blockIdx.x * BN_;

    A += (size_t)blockIdx.z * Kloop;                // K offset along A rows
    B += (size_t)blockIdx.z * Kloop * ldb;          // K offset down B
    Cout += (size_t)blockIdx.z * partStride;

    // A tile: 128x16 = 512 float4, 2 per thread
    const int arow0 = tid >> 2;
    const int arow1 = arow0 + 64;
    const int ac4 = (tid & 3) * 4;
    const float* gA0 = A + (size_t)(m0 + arow0) * lda + ac4;
    const float* gA1 = A + (size_t)(m0 + arow1) * lda + ac4;

    // B tile: 16xBN_ floats
    const int BQ = BN_ / 4;
    const int bkr0 = tid / BQ;
    const int bc0 = (tid % BQ) * 4;
    const float* gB0 = B + (size_t)bkr0 * ldb + n0 + bc0;
    const bool bp0 = (n0 + bc0) < Nd;
    const int bkr1 = (tid + 256) / BQ;
    const int bc1 = ((tid + 256) % BQ) * 4;
    const float* gB1 = B + (size_t)bkr1 * ldb + n0 + bc1;
    const bool bp1 = (n0 + bc1) < Nd;

    float acc[8][TN_];
    #pragma unroll
    for (int i = 0; i < 8; ++i)
        #pragma unroll
        for (int j = 0; j < TN_; ++j) acc[i][j] = 0.f;

    const int KT = Kloop / BK;

    // prefetch tile 0
    cpasync16(&As[0][arow0][ac4], gA0, true);
    cpasync16(&As[0][arow1][ac4], gA1, true);
    cpasync16(&Bs[0][bkr0][bc0], gB0, bp0);
    if (BN_ == 128) cpasync16(&Bs[0][bkr1][bc1], gB1, bp1);
    cp_commit();

    int buf = 0;
    for (int kt = 0; kt < KT; ++kt) {
        if (kt + 1 < KT) {
            int ko = (kt + 1) * BK;
            cpasync16(&As[buf ^ 1][arow0][ac4], gA0 + ko, true);
            cpasync16(&As[buf ^ 1][arow1][ac4], gA1 + ko, true);
            cpasync16(&Bs[buf ^ 1][bkr0][bc0], gB0 + (size_t)ko * ldb, bp0);
            if (BN_ == 128) cpasync16(&Bs[buf ^ 1][bkr1][bc1], gB1 + (size_t)ko * ldb, bp1);
            cp_commit();
            cp_wait1();
        } else {
            cp_wait0();
        }
        __syncthreads();

        #pragma unroll
        for (int k = 0; k < BK; ++k) {
            float a[8];
            #pragma unroll
            for (int i = 0; i < 8; ++i) a[i] = As[buf][ty * 8 + i][k];
            float b[TN_];
            #pragma unroll
            for (int j = 0; j < TN_; j += 4) {
                float4 v = *reinterpret_cast<const float4*>(&Bs[buf][k][tx * TN_ + j]);
                b[j] = v.x; b[j + 1] = v.y; b[j + 2] = v.z; b[j + 3] = v.w;
            }
            #pragma unroll
            for (int i = 0; i < 8; ++i)
                #pragma unroll
                for (int j = 0; j < TN_; ++j)
                    acc[i][j] += a[i] * b[j];
        }
        __syncthreads();
        buf ^= 1;
    }

    // epilogue: float4 stores (all shapes are 4-aligned in N)
    #pragma unroll
    for (int i = 0; i < 8; ++i) {
        int m = m0 + ty * 8 + i;
        #pragma unroll
        for (int j = 0; j < TN_; j += 4) {
            int n = n0 + tx * TN_ + j;
            if (n < Nd) {
                float4 v = make_float4(acc[i][j], acc[i][j + 1], acc[i][j + 2], acc[i][j + 3]);
                if (EPI) {
                    const float4 bb = *reinterpret_cast<const float4*>(&bias[n]);
                    v.x = fmaxf(v.x + bb.x, 0.f);
                    v.y = fmaxf(v.y + bb.y, 0.f);
                    v.z = fmaxf(v.z + bb.z, 0.f);
                    v.w = fmaxf(v.w + bb.w, 0.f);
                }
                *reinterpret_cast<float4*>(&Cout[(size_t)m * ldc + n]) = v;
            }
        }
    }
}

// ---------------- host orchestration ----------------
static float* run_prop(const int* nbr, const int* cnt, const float* dvec,
                       const float* feat, const float* w, int C,
                       float* u, float* va, float* vb) {
    int total = NN * C;
    k_scale_u<<<(total + 255) / 256, 256>>>(feat, dvec, u, va, C);
    float* vin = va;
    float* vout = vb;
    for (int k = 5; k >= 1; --k) {
        if (C > 1024) k_spmm<2><<<NN, 256>>>(nbr, cnt, vin, u, vout, w, k, C);
        else          k_spmm<1><<<NN, 256>>>(nbr, cnt, vin, u, vout, w, k, C);
        float* t = vin; vin = vout; vout = t;
    }
    return vin;
}

extern "C" void kernel_launch(void* const* d_in, const int* in_sizes, int n_in,
                              void* d_out, int out_size) {
    const float* x  = (const float*)d_in[0];
    const int*   ei = (const int*)  d_in[1];
    const float* w1 = (const float*)d_in[2];
    const float* w2 = (const float*)d_in[3];
    const float* w3 = (const float*)d_in[4];
    const float* W1 = (const float*)d_in[5];
    const float* b1 = (const float*)d_in[6];
    const float* W2 = (const float*)d_in[7];
    const float* b2 = (const float*)d_in[8];
    const float* W3 = (const float*)d_in[9];
    const float* b3 = (const float*)d_in[10];
    float* out = (float*)d_out;

    unsigned *adj, *rA, *rB;
    int *nbr, *cnt;
    float *dvec, *u, *va, *vb, *z, *h1, *gg, *h2, *g3, *g3p;
    cudaGetSymbolAddress((void**)&adj,  g_adj);
    cudaGetSymbolAddress((void**)&rA,   g_rA);
    cudaGetSymbolAddress((void**)&rB,   g_rB);
    cudaGetSymbolAddress((void**)&nbr,  g_nbr);
    cudaGetSymbolAddress((void**)&cnt,  g_cnt);
    cudaGetSymbolAddress((void**)&dvec, g_dvec);
    cudaGetSymbolAddress((void**)&u,    g_u);
    cudaGetSymbolAddress((void**)&va,   g_va);
    cudaGetSymbolAddress((void**)&vb,   g_vb);
    cudaGetSymbolAddress((void**)&z,    g_z);
    cudaGetSymbolAddress((void**)&h1,   g_h1);
    cudaGetSymbolAddress((void**)&gg,   g_gg);
    cudaGetSymbolAddress((void**)&h2,   g_h2);
    cudaGetSymbolAddress((void**)&g3,   g_g3);
    cudaGetSymbolAddress((void**)&g3p,  g_g3p);

    // ---- adjacency + neighbor lists + reach + deg ----
    k_zero_u32<<<(NN * WORDS + 255) / 256, 256>>>(adj, NN * WORDS);
    k_build_adj<<<EE / 256, 256>>>(ei, adj);
    k_build_list<<<NN / 256, 256>>>(adj, nbr, cnt);
    k_reach_init<<<(NN * WORDS + 255) / 256, 256>>>(adj, rA);
    k_reach_iter<<<NN, 64>>>(nbr, cnt, rA, rB);
    k_reach_iter<<<NN, 64>>>(nbr, cnt, rB, rA);
    k_reach_iter<<<NN, 64>>>(nbr, cnt, rA, rB);
    k_reach_iter<<<NN, 64>>>(nbr, cnt, rB, rA);
    k_deg<<<(NN + 255) / 256, 256>>>(rA, dvec);

    // ---- layer 1: h1 = relu((M1_hat x) W1 + b1) ----
    {
        float* v = run_prop(nbr, cnt, dvec, x, w1, C_IN, u, va, vb);
        k_scale_z<<<(NN * C_IN + 255) / 256, 256>>>(v, dvec, w1, z, C_IN);
        dim3 grid(H1D / 128, NN / BM, 1);
        k_gemm<128, 8, 1><<<grid, 256>>>(z, C_IN, W1, H1D, b1, h1, H1D, H1D, C_IN, 0);
    }

    // ---- layer 2: h2 = relu(M2_hat (h1 W2) + b2) ----
    {
        dim3 grid(H2D / 64, NN / BM, 1);
        k_gemm<64, 4, 0><<<grid, 256>>>(h1, H1D, W2, H2D, (const float*)0, gg, H2D, H2D, H1D, 0);
        float* v = run_prop(nbr, cnt, dvec, gg, w2, H2D, u, va, vb);
        k_final<<<(NN * H2D + 255) / 256, 256>>>(v, dvec, w2, b2, h2, H2D);
    }

    // ---- layer 3: out = relu(M3_hat (h2 W3) + b3), split-K GEMM ----
    {
        dim3 grid(1, NN / BM, SK3);
        k_gemm<64, 4, 0><<<grid, 256>>>(h2, H2D, W3, ODIM, (const float*)0,
                                        g3p, ODIM, ODIM, H2D / SK3, NN * ODIM);
        k_reduce_sk<<<(NN * ODIM + 255) / 256, 256>>>(g3p, g3, NN * ODIM);
        float* v = run_prop(nbr, cnt, dvec, g3, w3, ODIM, u, va, vb);
        k_final<<<(NN * ODIM + 255) / 256, 256>>>(v, dvec, w3, b3, out, ODIM);
    }
}

// round 4
// speedup vs baseline: 2.2584x; 1.3489x over previous
#include <cuda_runtime.h>
#include <cuda_bf16.h>

#define NN 2048
#define EE 65536
#define WORDS 64
#define NBMAX 2048
#define C_IN 128
#define H1D 3200
#define H2D 1600
#define ODIM 32
#define SK3 4

// ---------------- scratch (device globals) ----------------
__device__ unsigned g_adj[NN * WORDS];
__device__ unsigned g_rA [NN * WORDS];
__device__ unsigned g_rB [NN * WORDS];
__device__ int      g_nbr[(size_t)NN * NBMAX];
__device__ int      g_cnt[NN];
__device__ float    g_dvec[NN];
__device__ float    g_u  [NN * H2D];
__device__ float    g_va [NN * H2D];
__device__ float    g_vb [NN * H2D];
__device__ float    g_z  [NN * C_IN];
__device__ float    g_gg [NN * H2D];
__device__ float    g_h2 [NN * H2D];
__device__ float    g_g3 [NN * ODIM];
__device__ float    g_g3p[SK3 * NN * ODIM];
// bf16 split operands
__device__ __nv_bfloat16 g_zhi[NN * C_IN],  g_zlo[NN * C_IN];
__device__ __nv_bfloat16 g_w1hi[C_IN * H1D], g_w1lo[C_IN * H1D];
__device__ __nv_bfloat16 g_w2hi[H1D * H2D],  g_w2lo[H1D * H2D];
__device__ __nv_bfloat16 g_h1hi[(size_t)NN * H1D], g_h1lo[(size_t)NN * H1D];

// ---------------- utility kernels ----------------
__global__ void k_zero_u32(unsigned* p, int n) {
    int i = blockIdx.x * blockDim.x + threadIdx.x;
    if (i < n) p[i] = 0u;
}

__global__ void k_build_adj(const int* __restrict__ ei, unsigned* __restrict__ adj) {
    int e = blockIdx.x * blockDim.x + threadIdx.x;
    if (e < EE) {
        int src = ei[e];
        int dst = ei[EE + e];
        atomicOr(&adj[dst * WORDS + (src >> 5)], 1u << (src & 31));
    }
}

__global__ void k_build_list(const unsigned* __restrict__ adj,
                             int* __restrict__ nbr, int* __restrict__ cnt) {
    int u = blockIdx.x * blockDim.x + threadIdx.x;
    if (u >= NN) return;
    int c = 0;
    int* out = nbr + (size_t)u * NBMAX;
    for (int w = 0; w < WORDS; ++w) {
        unsigned bits = adj[u * WORDS + w];
        while (bits) {
            int b = __ffs(bits) - 1;
            bits &= bits - 1;
            if (c < NBMAX) out[c] = w * 32 + b;
            ++c;
        }
    }
    cnt[u] = (c < NBMAX) ? c : NBMAX;
}

__global__ void k_reach_init(const unsigned* __restrict__ adj, unsigned* __restrict__ R) {
    int i = blockIdx.x * blockDim.x + threadIdx.x;
    if (i < NN * WORDS) {
        int u = i >> 6, w = i & 63;
        unsigned v = adj[i];
        if ((u >> 5) == w) v |= 1u << (u & 31);
        R[i] = v;
    }
}

__global__ void k_reach_iter(const int* __restrict__ nbr, const int* __restrict__ cnt,
                             const unsigned* __restrict__ Rold, unsigned* __restrict__ Rnew) {
    int u = blockIdx.x;
    int w = threadIdx.x;
    int n = __ldg(&cnt[u]);
    const int* list = nbr + (size_t)u * NBMAX;
    unsigned acc = ((u >> 5) == w) ? (1u << (u & 31)) : 0u;
    int j = 0;
    for (; j + 4 <= n; j += 4) {
        int v0 = __ldg(list + j + 0), v1 = __ldg(list + j + 1);
        int v2 = __ldg(list + j + 2), v3 = __ldg(list + j + 3);
        unsigned r0 = Rold[v0 * WORDS + w];
        unsigned r1 = Rold[v1 * WORDS + w];
        unsigned r2 = Rold[v2 * WORDS + w];
        unsigned r3 = Rold[v3 * WORDS + w];
        acc |= (r0 | r1) | (r2 | r3);
    }
    for (; j < n; ++j) acc |= Rold[__ldg(list + j) * WORDS + w];
    Rnew[u * WORDS + w] = acc;
}

__global__ void k_deg(const unsigned* __restrict__ R, float* __restrict__ d) {
    int u = blockIdx.x * blockDim.x + threadIdx.x;
    if (u < NN) {
        int c = 0;
        #pragma unroll 8
        for (int w = 0; w < WORDS; ++w) c += __popc(R[u * WORDS + w]);
        d[u] = (c > 0) ? rsqrtf((float)c) : 0.0f;
    }
}

__global__ void k_scale_u(const float* __restrict__ feat, const float* __restrict__ d,
                          float* __restrict__ u, float* __restrict__ v, int C) {
    int i = blockIdx.x * blockDim.x + threadIdx.x;
    if (i < NN * C) {
        float val = d[i / C] * feat[i];
        u[i] = val;
        v[i] = val;
    }
}

template <int NV>
__global__ __launch_bounds__(256)
void k_spmm(const int* __restrict__ nbr, const int* __restrict__ cnt,
            const float* __restrict__ vin, const float* __restrict__ uvec,
            float* __restrict__ vout,
            const float* __restrict__ wvec, int widx, int C) {
    int u = blockIdx.x;
    int t = threadIdx.x;
    int n = __ldg(&cnt[u]);
    const int* list = nbr + (size_t)u * NBMAX;
    const int C4 = C >> 2;
    float wk = __ldg(&wvec[widx]);

    float4 acc[NV];
    #pragma unroll
    for (int q = 0; q < NV; ++q) acc[q] = make_float4(0.f, 0.f, 0.f, 0.f);

    int j = 0;
    for (; j + 4 <= n; j += 4) {
        int v0 = __ldg(list + j + 0), v1 = __ldg(list + j + 1);
        int v2 = __ldg(list + j + 2), v3 = __ldg(list + j + 3);
        const float4* r0 = reinterpret_cast<const float4*>(vin + (size_t)v0 * C);
        const float4* r1 = reinterpret_cast<const float4*>(vin + (size_t)v1 * C);
        const float4* r2 = reinterpret_cast<const float4*>(vin + (size_t)v2 * C);
        const float4* r3 = reinterpret_cast<const float4*>(vin + (size_t)v3 * C);
        #pragma unroll
        for (int q = 0; q < NV; ++q) {
            int idx = t + q * 256;
            if (idx < C4) {
                float4 x0 = __ldg(r0 + idx);
                float4 x1 = __ldg(r1 + idx);
                float4 x2 = __ldg(r2 + idx);
                float4 x3 = __ldg(r3 + idx);
                acc[q].x += (x0.x + x1.x) + (x2.x + x3.x);
                acc[q].y += (x0.y + x1.y) + (x2.y + x3.y);
                acc[q].z += (x0.z + x1.z) + (x2.z + x3.z);
                acc[q].w += (x0.w + x1.w) + (x2.w + x3.w);
            }
        }
    }
    for (; j < n; ++j) {
        int v = __ldg(list + j);
        const float4* r = reinterpret_cast<const float4*>(vin + (size_t)v * C);
        #pragma unroll
        for (int q = 0; q < NV; ++q) {
            int idx = t + q * 256;
            if (idx < C4) {
                float4 x = __ldg(r + idx);
                acc[q].x += x.x; acc[q].y += x.y; acc[q].z += x.z; acc[q].w += x.w;
            }
        }
    }
    const float4* urow = reinterpret_cast<const float4*>(uvec + (size_t)u * C);
    float4* orow = reinterpret_cast<float4*>(vout + (size_t)u * C);
    #pragma unroll
    for (int q = 0; q < NV; ++q) {
        int idx = t + q * 256;
        if (idx < C4) {
            float4 uu = urow[idx];
            float4 o;
            o.x = uu.x + wk * acc[q].x;
            o.y = uu.y + wk * acc[q].y;
            o.z = uu.z + wk * acc[q].z;
            o.w = uu.w + wk * acc[q].w;
            orow[idx] = o;
        }
    }
}

__global__ void k_scale_z(const float* __restrict__ v, const float* __restrict__ d,
                          const float* __restrict__ wvec, float* __restrict__ z, int C) {
    int i = blockIdx.x * blockDim.x + threadIdx.x;
    if (i < NN * C) z[i] = wvec[0] * d[i / C] * v[i];
}

__global__ void k_final(const float* __restrict__ v, const float* __restrict__ d,
                        const float* __restrict__ wvec, const float* __restrict__ bias,
                        float* __restrict__ out, int C) {
    int i = blockIdx.x * blockDim.x + threadIdx.x;
    if (i < NN * C) {
        float val = wvec[0] * d[i / C] * v[i] + bias[i % C];
        out[i] = fmaxf(val, 0.0f);
    }
}

__global__ void k_reduce_sk(const float* __restrict__ p, float* __restrict__ out, int n) {
    int i = blockIdx.x * blockDim.x + threadIdx.x;
    if (i < n) {
        float s = 0.f;
        #pragma unroll
        for (int k = 0; k < SK3; ++k) s += p[(size_t)k * n + i];
        out[i] = s;
    }
}

// split fp32 -> (hi, lo) bf16
__global__ void k_split(const float* __restrict__ s, __nv_bfloat16* __restrict__ hi,
                        __nv_bfloat16* __restrict__ lo, int n) {
    int i = blockIdx.x * blockDim.x + threadIdx.x;
    if (i < n) {
        float x = s[i];
        __nv_bfloat16 h = __float2bfloat16_rn(x);
        float r = x - __bfloat162float(h);
        hi[i] = h;
        lo[i] = __float2bfloat16_rn(r);
    }
}

// ---------------- cp.async helpers ----------------
__device__ __forceinline__ void cpasync16(void* s, const void* g, bool p) {
    unsigned sa = (unsigned)__cvta_generic_to_shared(s);
    asm volatile("cp.async.cg.shared.global [%0], [%1], 16, %2;"
                 :: "r"(sa), "l"(g), "r"(p ? 16 : 0));
}
__device__ __forceinline__ void cp_commit() { asm volatile("cp.async.commit_group;" ::: "memory"); }
__device__ __forceinline__ void cp_wait0()  { asm volatile("cp.async.wait_group 0;" ::: "memory"); }
__device__ __forceinline__ void cp_wait1()  { asm volatile("cp.async.wait_group 1;" ::: "memory"); }

// ---------------- bf16 split tensor-core GEMM ----------------
#define TBM 128
#define TBN 128
#define TBK 32
#define ASTR 40     // A smem row stride (bf16), conflict-free for ldmatrix
#define BSTR 136    // B smem row stride (bf16)
#define ABUF (TBM * ASTR)       // 5120 elems per buffer
#define BBUF (TBK * BSTR)       // 4352 elems per buffer
#define SMEM_ELEMS (4 * ABUF + 4 * BBUF)       // hi+lo, double buffered
#define SMEM_BYTES (SMEM_ELEMS * 2)            // 75776

__device__ __forceinline__ unsigned sptr(const void* p) {
    return (unsigned)__cvta_generic_to_shared(p);
}
__device__ __forceinline__ void ldsm4(unsigned& r0, unsigned& r1, unsigned& r2, unsigned& r3, unsigned a) {
    asm volatile("ldmatrix.sync.aligned.m8n8.x4.shared.b16 {%0,%1,%2,%3}, [%4];"
                 : "=r"(r0), "=r"(r1), "=r"(r2), "=r"(r3) : "r"(a));
}
__device__ __forceinline__ void ldsm4t(unsigned& r0, unsigned& r1, unsigned& r2, unsigned& r3, unsigned a) {
    asm volatile("ldmatrix.sync.aligned.m8n8.x4.trans.shared.b16 {%0,%1,%2,%3}, [%4];"
                 : "=r"(r0), "=r"(r1), "=r"(r2), "=r"(r3) : "r"(a));
}
__device__ __forceinline__ void mma16816(float* c, const unsigned* a, unsigned b0, unsigned b1) {
    asm volatile("mma.sync.aligned.m16n8k16.row.col.f32.bf16.bf16.f32 "
                 "{%0,%1,%2,%3},{%4,%5,%6,%7},{%8,%9},{%0,%1,%2,%3};"
                 : "+f"(c[0]), "+f"(c[1]), "+f"(c[2]), "+f"(c[3])
                 : "r"(a[0]), "r"(a[1]), "r"(a[2]), "r"(a[3]), "r"(b0), "r"(b1));
}

// D = Ahi*Bhi + Ahi*Blo + Alo*Bhi over K.  A[M,K] row-major, B[K,N] row-major.
// EPI=1: +bias, relu, write split bf16 (Chi/Clo, ld=Nd).  EPI=0: fp32 out Cf (ldc), col<Nd guard.
template<int EPI>
__global__ __launch_bounds__(256, 1)
void k_gemm_bf16(const __nv_bfloat16* __restrict__ Ahi, const __nv_bfloat16* __restrict__ Alo, int lda,
                 const __nv_bfloat16* __restrict__ Bhi, const __nv_bfloat16* __restrict__ Blo, int ldb,
                 const float* __restrict__ bias,
                 float* __restrict__ Cf, __nv_bfloat16* __restrict__ Chi, __nv_bfloat16* __restrict__ Clo,
                 int ldc, int Nd, int K) {
    extern __shared__ __nv_bfloat16 sm[];
    __nv_bfloat16* sAh = sm;
    __nv_bfloat16* sAl = sAh + 2 * ABUF;
    __nv_bfloat16* sBh = sAl + 2 * ABUF;
    __nv_bfloat16* sBl = sBh + 2 * BBUF;

    const int tid = threadIdx.x;
    const int wid = tid >> 5, lane = tid & 31;
    const int wm = (wid & 1) * 64;       // warp m offset (2 warps along M)
    const int wn = (wid >> 1) * 32;      // warp n offset (4 warps along N)
    const int m0 = blockIdx.y * TBM, n0 = blockIdx.x * TBN;

    // cp.async chunk mapping
    const int a_r = tid >> 2;            // rows: a_r, a_r+64
    const int a_c = (tid & 3) << 3;      // bf16 col (8-elem chunks)
    const int b_r = tid >> 4;            // rows: b_r, b_r+16
    const int b_c = (tid & 15) << 3;
    const bool pb = (n0 + b_c) < Nd;

    const __nv_bfloat16* gAh0 = Ahi + (size_t)(m0 + a_r) * lda + a_c;
    const __nv_bfloat16* gAh1 = Ahi + (size_t)(m0 + a_r + 64) * lda + a_c;
    const __nv_bfloat16* gAl0 = Alo + (size_t)(m0 + a_r) * lda + a_c;
    const __nv_bfloat16* gAl1 = Alo + (size_t)(m0 + a_r + 64) * lda + a_c;
    const __nv_bfloat16* gBh0 = Bhi + (size_t)b_r * ldb + n0 + b_c;
    const __nv_bfloat16* gBh1 = Bhi + (size_t)(b_r + 16) * ldb + n0 + b_c;
    const __nv_bfloat16* gBl0 = Blo + (size_t)b_r * ldb + n0 + b_c;
    const __nv_bfloat16* gBl1 = Blo + (size_t)(b_r + 16) * ldb + n0 + b_c;

    float acc[4][4][4];
    #pragma unroll
    for (int i = 0; i < 4; ++i)
        #pragma unroll
        for (int j = 0; j < 4; ++j)
            #pragma unroll
            for (int q = 0; q < 4; ++q) acc[i][j][q] = 0.f;

    const int KT = K / TBK;

    // prologue prefetch (k0 = 0)
    cpasync16(sAh + a_r * ASTR + a_c, gAh0, true);
    cpasync16(sAh + (a_r + 64) * ASTR + a_c, gAh1, true);
    cpasync16(sAl + a_r * ASTR + a_c, gAl0, true);
    cpasync16(sAl + (a_r + 64) * ASTR + a_c, gAl1, true);
    cpasync16(sBh + b_r * BSTR + b_c, gBh0, pb);
    cpasync16(sBh + (b_r + 16) * BSTR + b_c, gBh1, pb);
    cpasync16(sBl + b_r * BSTR + b_c, gBl0, pb);
    cpasync16(sBl + (b_r + 16) * BSTR + b_c, gBl1, pb);
    cp_commit();

    const int l16 = lane & 15;
    const int hsel = (lane >> 4) << 3;   // +8 cols for lanes 16-31
    const int bg = lane >> 3, bl8 = lane & 7;
    const int bkoff = ((bg & 1) << 3) + bl8;      // k row within 16
    const int bnoff = wn + ((bg >> 1) << 3);      // n col

    int buf = 0;
    for (int kt = 0; kt < KT; ++kt) {
        if (kt + 1 < KT) {
            int ko = (kt + 1) * TBK;
            int ob = (buf ^ 1);
            cpasync16(sAh + ob * ABUF + a_r * ASTR + a_c, gAh0 + ko, true);
            cpasync16(sAh + ob * ABUF + (a_r + 64) * ASTR + a_c, gAh1 + ko, true);
            cpasync16(sAl + ob * ABUF + a_r * ASTR + a_c, gAl0 + ko, true);
            cpasync16(sAl + ob * ABUF + (a_r + 64) * ASTR + a_c, gAl1 + ko, true);
            cpasync16(sBh + ob * BBUF + b_r * BSTR + b_c, gBh0 + (size_t)ko * ldb, pb);
            cpasync16(sBh + ob * BBUF + (b_r + 16) * BSTR + b_c, gBh1 + (size_t)ko * ldb, pb);
            cpasync16(sBl + ob * BBUF + b_r * BSTR + b_c, gBl0 + (size_t)ko * ldb, pb);
            cpasync16(sBl + ob * BBUF + (b_r + 16) * BSTR + b_c, gBl1 + (size_t)ko * ldb, pb);
            cp_commit();
            cp_wait1();
        } else {
            cp_wait0();
        }
        __syncthreads();

        #pragma unroll
        for (int ks = 0; ks < 2; ++ks) {
            const int ko = ks * 16;
            // B fragments: 2 n16-chunks, hi+lo
            unsigned bh[8], blr[8];
            {
                unsigned ab = sptr(sBh + buf * BBUF + (ko + bkoff) * BSTR + bnoff);
                ldsm4t(bh[0], bh[1], bh[2], bh[3], ab);
                ldsm4t(bh[4], bh[5], bh[6], bh[7], ab + 32);       // +16 bf16 cols
                unsigned al = sptr(sBl + buf * BBUF + (ko + bkoff) * BSTR + bnoff);
                ldsm4t(blr[0], blr[1], blr[2], blr[3], al);
                ldsm4t(blr[4], blr[5], blr[6], blr[7], al + 32);
            }
            #pragma unroll
            for (int mi = 0; mi < 4; ++mi) {
                unsigned ah[4], alr[4];
                unsigned aa = sptr(sAh + buf * ABUF + (wm + mi * 16 + l16) * ASTR + ko + hsel);
                ldsm4(ah[0], ah[1], ah[2], ah[3], aa);
                unsigned aal = sptr(sAl + buf * ABUF + (wm + mi * 16 + l16) * ASTR + ko + hsel);
                ldsm4(alr[0], alr[1], alr[2], alr[3], aal);
                #pragma unroll
                for (int nj = 0; nj < 4; ++nj) {
                    int bi = (nj >> 1) * 4 + (nj & 1) * 2;
                    mma16816(acc[mi][nj], ah, bh[bi], bh[bi + 1]);    // hi*hi
                    mma16816(acc[mi][nj], ah, blr[bi], blr[bi + 1]);  // hi*lo
                    mma16816(acc[mi][nj], alr, bh[bi], bh[bi + 1]);   // lo*hi
                }
            }
        }
        __syncthreads();
        buf ^= 1;
    }

    // epilogue
    const int er = lane >> 2;
    const int ec = (lane & 3) << 1;
    #pragma unroll
    for (int mi = 0; mi < 4; ++mi) {
        #pragma unroll
        for (int nj = 0; nj < 4; ++nj) {
            int row = m0 + wm + mi * 16 + er;
            int col = n0 + wn + nj * 8 + ec;
            float* a = acc[mi][nj];
            if (EPI) {
                float bv0 = bias[col], bv1 = bias[col + 1];
                #pragma unroll
                for (int h = 0; h < 2; ++h) {
                    int r = row + h * 8;
                    float v0 = fmaxf(a[h * 2 + 0] + bv0, 0.f);
                    float v1 = fmaxf(a[h * 2 + 1] + bv1, 0.f);
                    __nv_bfloat16 h0 = __float2bfloat16_rn(v0);
                    __nv_bfloat16 h1 = __float2bfloat16_rn(v1);
                    __nv_bfloat162 hp; hp.x = h0; hp.y = h1;
                    __nv_bfloat162 lp;
                    lp.x = __float2bfloat16_rn(v0 - __bfloat162float(h0));
                    lp.y = __float2bfloat16_rn(v1 - __bfloat162float(h1));
                    *reinterpret_cast<__nv_bfloat162*>(&Chi[(size_t)r * Nd + col]) = hp;
                    *reinterpret_cast<__nv_bfloat162*>(&Clo[(size_t)r * Nd + col]) = lp;
                }
            } else {
                if (col < Nd) {
                    *reinterpret_cast<float2*>(&Cf[(size_t)row * ldc + col]) = make_float2(a[0], a[1]);
                    *reinterpret_cast<float2*>(&Cf[(size_t)(row + 8) * ldc + col]) = make_float2(a[2], a[3]);
                }
            }
        }
    }
}

// ---------------- fp32 GEMM (kept for tiny GEMM3, split-K) ----------------
#define BM 128
#define BK 16

template<int BN_, int TN_>
__global__ __launch_bounds__(256)
void k_gemm(const float* __restrict__ A, int lda,
            const float* __restrict__ B, int ldb,
            float* __restrict__ Cout, int ldc,
            int Nd, int Kloop, int partStride) {
    __shared__ float As[2][BM][BK];
    __shared__ float Bs[2][BK][BN_];

    const int tid = threadIdx.x;
    const int tx = tid & 15;
    const int ty = tid >> 4;
    const int m0 = blockIdx.y * BM;
    const int n0 = blockIdx.x * BN_;

    A += (size_t)blockIdx.z * Kloop;
    B += (size_t)blockIdx.z * Kloop * ldb;
    Cout += (size_t)blockIdx.z * partStride;

    const int arow0 = tid >> 2;
    const int arow1 = arow0 + 64;
    const int ac4 = (tid & 3) * 4;
    const float* gA0 = A + (size_t)(m0 + arow0) * lda + ac4;
    const float* gA1 = A + (size_t)(m0 + arow1) * lda + ac4;

    const int BQ = BN_ / 4;
    const int bkr0 = tid / BQ;
    const int bc0 = (tid % BQ) * 4;
    const float* gB0 = B + (size_t)bkr0 * ldb + n0 + bc0;
    const bool bp0 = (n0 + bc0) < Nd;

    float acc[8][TN_];
    #pragma unroll
    for (int i = 0; i < 8; ++i)
        #pragma unroll
        for (int j = 0; j < TN_; ++j) acc[i][j] = 0.f;

    const int KT = Kloop / BK;

    cpasync16(&As[0][arow0][ac4], gA0, true);
    cpasync16(&As[0][arow1][ac4], gA1, true);
    cpasync16(&Bs[0][bkr0][bc0], gB0, bp0);
    cp_commit();

    int buf = 0;
    for (int kt = 0; kt < KT; ++kt) {
        if (kt + 1 < KT) {
            int ko = (kt + 1) * BK;
            cpasync16(&As[buf ^ 1][arow0][ac4], gA0 + ko, true);
            cpasync16(&As[buf ^ 1][arow1][ac4], gA1 + ko, true);
            cpasync16(&Bs[buf ^ 1][bkr0][bc0], gB0 + (size_t)ko * ldb, bp0);
            cp_commit();
            cp_wait1();
        } else {
            cp_wait0();
        }
        __syncthreads();

        #pragma unroll
        for (int k = 0; k < BK; ++k) {
            float a[8];
            #pragma unroll
            for (int i = 0; i < 8; ++i) a[i] = As[buf][ty * 8 + i][k];
            float b[TN_];
            #pragma unroll
            for (int j = 0; j < TN_; j += 4) {
                float4 v = *reinterpret_cast<const float4*>(&Bs[buf][k][tx * TN_ + j]);
                b[j] = v.x; b[j + 1] = v.y; b[j + 2] = v.z; b[j + 3] = v.w;
            }
            #pragma unroll
            for (int i = 0; i < 8; ++i)
                #pragma unroll
                for (int j = 0; j < TN_; ++j)
                    acc[i][j] += a[i] * b[j];
        }
        __syncthreads();
        buf ^= 1;
    }

    #pragma unroll
    for (int i = 0; i < 8; ++i) {
        int m = m0 + ty * 8 + i;
        #pragma unroll
        for (int j = 0; j < TN_; j += 4) {
            int n = n0 + tx * TN_ + j;
            if (n < Nd) {
                float4 v = make_float4(acc[i][j], acc[i][j + 1], acc[i][j + 2], acc[i][j + 3]);
                *reinterpret_cast<float4*>(&Cout[(size_t)m * ldc + n]) = v;
            }
        }
    }
}

// ---------------- host orchestration ----------------
static float* run_prop(const int* nbr, const int* cnt, const float* dvec,
                       const float* feat, const float* w, int C,
                       float* u, float* va, float* vb) {
    int total = NN * C;
    k_scale_u<<<(total + 255) / 256, 256>>>(feat, dvec, u, va, C);
    float* vin = va;
    float* vout = vb;
    for (int k = 5; k >= 1; --k) {
        if (C > 1024) k_spmm<2><<<NN, 256>>>(nbr, cnt, vin, u, vout, w, k, C);
        else          k_spmm<1><<<NN, 256>>>(nbr, cnt, vin, u, vout, w, k, C);
        float* t = vin; vin = vout; vout = t;
    }
    return vin;
}

extern "C" void kernel_launch(void* const* d_in, const int* in_sizes, int n_in,
                              void* d_out, int out_size) {
    const float* x  = (const float*)d_in[0];
    const int*   ei = (const int*)  d_in[1];
    const float* w1 = (const float*)d_in[2];
    const float* w2 = (const float*)d_in[3];
    const float* w3 = (const float*)d_in[4];
    const float* W1 = (const float*)d_in[5];
    const float* b1 = (const float*)d_in[6];
    const float* W2 = (const float*)d_in[7];
    const float* b2 = (const float*)d_in[8];
    const float* W3 = (const float*)d_in[9];
    const float* b3 = (const float*)d_in[10];
    float* out = (float*)d_out;

    unsigned *adj, *rA, *rB;
    int *nbr, *cnt;
    float *dvec, *u, *va, *vb, *z, *gg, *h2, *g3, *g3p;
    __nv_bfloat16 *zhi, *zlo, *w1hi, *w1lo, *w2hi, *w2lo, *h1hi, *h1lo;
    cudaGetSymbolAddress((void**)&adj,  g_adj);
    cudaGetSymbolAddress((void**)&rA,   g_rA);
    cudaGetSymbolAddress((void**)&rB,   g_rB);
    cudaGetSymbolAddress((void**)&nbr,  g_nbr);
    cudaGetSymbolAddress((void**)&cnt,  g_cnt);
    cudaGetSymbolAddress((void**)&dvec, g_dvec);
    cudaGetSymbolAddress((void**)&u,    g_u);
    cudaGetSymbolAddress((void**)&va,   g_va);
    cudaGetSymbolAddress((void**)&vb,   g_vb);
    cudaGetSymbolAddress((void**)&z,    g_z);
    cudaGetSymbolAddress((void**)&gg,   g_gg);
    cudaGetSymbolAddress((void**)&h2,   g_h2);
    cudaGetSymbolAddress((void**)&g3,   g_g3);
    cudaGetSymbolAddress((void**)&g3p,  g_g3p);
    cudaGetSymbolAddress((void**)&zhi,  g_zhi);
    cudaGetSymbolAddress((void**)&zlo,  g_zlo);
    cudaGetSymbolAddress((void**)&w1hi, g_w1hi);
    cudaGetSymbolAddress((void**)&w1lo, g_w1lo);
    cudaGetSymbolAddress((void**)&w2hi, g_w2hi);
    cudaGetSymbolAddress((void**)&w2lo, g_w2lo);
    cudaGetSymbolAddress((void**)&h1hi, g_h1hi);
    cudaGetSymbolAddress((void**)&h1lo, g_h1lo);

    cudaFuncSetAttribute(k_gemm_bf16<0>, cudaFuncAttributeMaxDynamicSharedMemorySize, SMEM_BYTES);
    cudaFuncSetAttribute(k_gemm_bf16<1>, cudaFuncAttributeMaxDynamicSharedMemorySize, SMEM_BYTES);

    // ---- adjacency + neighbor lists + reach + deg ----
    k_zero_u32<<<(NN * WORDS + 255) / 256, 256>>>(adj, NN * WORDS);
    k_build_adj<<<EE / 256, 256>>>(ei, adj);
    k_build_list<<<NN / 256, 256>>>(adj, nbr, cnt);
    k_reach_init<<<(NN * WORDS + 255) / 256, 256>>>(adj, rA);
    k_reach_iter<<<NN, 64>>>(nbr, cnt, rA, rB);
    k_reach_iter<<<NN, 64>>>(nbr, cnt, rB, rA);
    k_reach_iter<<<NN, 64>>>(nbr, cnt, rA, rB);
    k_reach_iter<<<NN, 64>>>(nbr, cnt, rB, rA);
    k_deg<<<(NN + 255) / 256, 256>>>(rA, dvec);

    // weight splits (independent of propagation; issue early)
    k_split<<<(C_IN * H1D + 255) / 256, 256>>>(W1, w1hi, w1lo, C_IN * H1D);
    k_split<<<(H1D * H2D + 255) / 256, 256>>>(W2, w2hi, w2lo, H1D * H2D);

    // ---- layer 1: h1 = relu((M1_hat x) W1 + b1), split-bf16 output ----
    {
        float* v = run_prop(nbr, cnt, dvec, x, w1, C_IN, u, va, vb);
        k_scale_z<<<(NN * C_IN + 255) / 256, 256>>>(v, dvec, w1, z, C_IN);
        k_split<<<(NN * C_IN + 255) / 256, 256>>>(z, zhi, zlo, NN * C_IN);
        dim3 grid(H1D / TBN, NN / TBM, 1);
        k_gemm_bf16<1><<<grid, 256, SMEM_BYTES>>>(zhi, zlo, C_IN, w1hi, w1lo, H1D,
                                                  b1, (float*)0, h1hi, h1lo, H1D, H1D, C_IN);
    }

    // ---- layer 2: h2 = relu(M2_hat (h1 W2) + b2) ----
    {
        dim3 grid((H2D + TBN - 1) / TBN, NN / TBM, 1);
        k_gemm_bf16<0><<<grid, 256, SMEM_BYTES>>>(h1hi, h1lo, H1D, w2hi, w2lo, H2D,
                                                  (const float*)0, gg, (__nv_bfloat16*)0,
                                                  (__nv_bfloat16*)0, H2D, H2D, H1D);
        float* v = run_prop(nbr, cnt, dvec, gg, w2, H2D, u, va, vb);
        k_final<<<(NN * H2D + 255) / 256, 256>>>(v, dvec, w2, b2, h2, H2D);
    }

    // ---- layer 3: out = relu(M3_hat (h2 W3) + b3), fp32 split-K GEMM ----
    {
        dim3 grid(1, NN / BM, SK3);
        k_gemm<64, 4><<<grid, 256>>>(h2, H2D, W3, ODIM, g3p, ODIM, ODIM, H2D / SK3, NN * ODIM);
        k_reduce_sk<<<(NN * ODIM + 255) / 256, 256>>>(g3p, g3, NN * ODIM);
        float* v = run_prop(nbr, cnt, dvec, g3, w3, ODIM, u, va, vb);
        k_final<<<(NN * ODIM + 255) / 256, 256>>>(v, dvec, w3, b3, out, ODIM);
    }
}